// round 2
// baseline (speedup 1.0000x reference)
#include <cuda_runtime.h>

#define N_NODES   100000
#define HIDDEN    48
#define N_TRIPLES 2000000
#define UV_ROWS   16

__device__ __align__(16) float g_u[N_NODES * HIDDEN];
__device__ __align__(16) float g_v[N_NODES * HIDDEN];
__device__ __align__(16) float g_agg[N_NODES * HIDDEN];
__device__ __align__(16) float g_cnt[N_NODES];
__device__ __align__(16) float g_C2[HIDDEN * HIDDEN];

// ---------------------------------------------------------------------------
// Zero the accumulators (must run every launch; graph replays require it)
// ---------------------------------------------------------------------------
__global__ void zero_kernel() {
    int i = blockIdx.x * blockDim.x + threadIdx.x;
    int stride = gridDim.x * blockDim.x;
    float4* a = (float4*)g_agg;
    const int n4 = N_NODES * HIDDEN / 4;
    for (int k = i; k < n4; k += stride) a[k] = make_float4(0.f, 0.f, 0.f, 0.f);
    for (int k = i; k < N_NODES; k += stride) g_cnt[k] = 0.f;
}

// ---------------------------------------------------------------------------
// C2[k][o] = sum_j W3[j][k] * Wu[o][48+j]   (48x48, trivial)
// ---------------------------------------------------------------------------
__global__ void prep_kernel(const float* __restrict__ W3,
                            const float* __restrict__ Wu) {
    int i = blockIdx.x * blockDim.x + threadIdx.x;
    if (i < HIDDEN * HIDDEN) {
        int k = i / HIDDEN, o = i % HIDDEN;
        float s = 0.f;
        #pragma unroll
        for (int j = 0; j < HIDDEN; j++)
            s = fmaf(W3[j * HIDDEN + k], Wu[o * 2 * HIDDEN + HIDDEN + j], s);
        g_C2[i] = s;
    }
}

// ---------------------------------------------------------------------------
// u[n][o] = sum_c h[n][c] * Wu[o][c];   v[n][o] = sum_k h[n][k] * C2[k][o]
// blockDim (48, UV_ROWS)
// ---------------------------------------------------------------------------
__global__ void uv_kernel(const float* __restrict__ h,
                          const float* __restrict__ Wu) {
    __shared__ float sA[HIDDEN][HIDDEN];   // sA[k][o] = Wu[o][k]
    __shared__ float sC[HIDDEN][HIDDEN];   // sC[k][o] = C2[k][o]
    __shared__ float sh[UV_ROWS][HIDDEN];

    int tx = threadIdx.x;      // 0..47 (output col)
    int ty = threadIdx.y;      // 0..UV_ROWS-1 (row in tile)
    int tid = ty * HIDDEN + tx;
    const int nthr = HIDDEN * UV_ROWS;

    for (int i = tid; i < HIDDEN * HIDDEN; i += nthr) {
        int k = i / HIDDEN, o = i % HIDDEN;
        sA[k][o] = Wu[o * 2 * HIDDEN + k];
        sC[k][o] = g_C2[i];
    }
    int row = blockIdx.x * UV_ROWS + ty;
    if (row < N_NODES) sh[ty][tx] = h[row * HIDDEN + tx];
    __syncthreads();
    if (row >= N_NODES) return;

    float a = 0.f, b = 0.f;
    #pragma unroll
    for (int k = 0; k < HIDDEN; k++) {
        float hv = sh[ty][k];
        a = fmaf(hv, sA[k][tx], a);
        b = fmaf(hv, sC[k][tx], b);
    }
    g_u[row * HIDDEN + tx] = a;
    g_v[row * HIDDEN + tx] = b;
}

// ---------------------------------------------------------------------------
// Per-triple gather + leaky + weighted atomic scatter.
// 2 triples per warp: lanes [0..15] -> triple 2p, [16..31] -> triple 2p+1.
// Within each half: lanes j<12 handle float4 chunk j; lane j==12 counts.
// NOTE: tb_index is int32 (JAX x64 disabled downgrades the requested int64).
// ---------------------------------------------------------------------------
__global__ void triple_kernel(const int* __restrict__ idx,
                              const float* __restrict__ d1a,
                              const float* __restrict__ d2a) {
    int gtid = blockIdx.x * blockDim.x + threadIdx.x;
    int warpId = gtid >> 5;
    int nWarps = (gridDim.x * blockDim.x) >> 5;
    int lane = threadIdx.x & 31;
    int half = lane >> 4;
    int j = lane & 15;
    const int nPairs = N_TRIPLES / 2;

    for (int p = warpId; p < nPairs; p += nWarps) {
        int t = 2 * p + half;
        int b = 3 * t;
        int c  = idx[b];
        int n1 = idx[b + 1];
        int n2 = idx[b + 2];
        float d1 = __ldg(d1a + t);
        float d2 = __ldg(d2a + t);
        float w = 1.0f + 0.3f * (fabsf(d1 - d2) / (fmaxf(d1, d2) + 1e-8f));

        if (j < 12) {
            const float4* pu = (const float4*)(g_u + c  * HIDDEN) + j;
            const float4* p1 = (const float4*)(g_v + n1 * HIDDEN) + j;
            const float4* p2 = (const float4*)(g_v + n2 * HIDDEN) + j;
            float4 uu = *pu;
            float4 v1 = *p1;
            float4 v2 = *p2;
            float x0 = uu.x + v1.x + v2.x;
            float x1 = uu.y + v1.y + v2.y;
            float x2 = uu.z + v1.z + v2.z;
            float x3 = uu.w + v1.w + v2.w;
            float dx = (x0 > 0.f ? x0 : 0.01f * x0) * w;
            float dy = (x1 > 0.f ? x1 : 0.01f * x1) * w;
            float dz = (x2 > 0.f ? x2 : 0.01f * x2) * w;
            float dw = (x3 > 0.f ? x3 : 0.01f * x3) * w;
            float* dst = g_agg + c * HIDDEN + 4 * j;
            asm volatile("red.global.add.v4.f32 [%0], {%1, %2, %3, %4};"
                         :: "l"(dst), "f"(dx), "f"(dy), "f"(dz), "f"(dw)
                         : "memory");
        } else if (j == 12) {
            atomicAdd(&g_cnt[c], 1.0f);
        }
    }
}

// ---------------------------------------------------------------------------
// out = LayerNorm(h + agg / sqrt(max(cnt,1))) * gamma + beta
// blockDim (16,16): 16 rows/block, each thread handles 3 consecutive cols,
// 16-lane shuffle reduction (xor masks <= 8 stay within the 16-lane group).
// ---------------------------------------------------------------------------
__global__ void final_kernel(const float* __restrict__ h,
                             const float* __restrict__ gamma,
                             const float* __restrict__ beta,
                             float* __restrict__ out) {
    int tx = threadIdx.x;  // 0..15
    int ty = threadIdx.y;  // 0..15
    int row = blockIdx.x * 16 + ty;
    if (row >= N_NODES) return;

    float rs = rsqrtf(fmaxf(g_cnt[row], 1.0f));
    int base = row * HIDDEN + tx * 3;
    float x0 = h[base]     + g_agg[base]     * rs;
    float x1 = h[base + 1] + g_agg[base + 1] * rs;
    float x2 = h[base + 2] + g_agg[base + 2] * rs;

    float s = x0 + x1 + x2;
    #pragma unroll
    for (int m = 8; m; m >>= 1) s += __shfl_xor_sync(0xffffffffu, s, m);
    float mu = s * (1.f / 48.f);

    float e0 = x0 - mu, e1 = x1 - mu, e2 = x2 - mu;
    float q = e0 * e0 + e1 * e1 + e2 * e2;
    #pragma unroll
    for (int m = 8; m; m >>= 1) q += __shfl_xor_sync(0xffffffffu, q, m);
    float inv = rsqrtf(q * (1.f / 48.f) + 1e-5f);

    int o = tx * 3;
    out[base]     = e0 * inv * gamma[o]     + beta[o];
    out[base + 1] = e1 * inv * gamma[o + 1] + beta[o + 1];
    out[base + 2] = e2 * inv * gamma[o + 2] + beta[o + 2];
}

// ---------------------------------------------------------------------------
extern "C" void kernel_launch(void* const* d_in, const int* in_sizes, int n_in,
                              void* d_out, int out_size) {
    const float* h     = (const float*)d_in[0];
    const int*   idx   = (const int*)d_in[1];
    const float* d1    = (const float*)d_in[2];
    const float* d2    = (const float*)d_in[3];
    const float* W3    = (const float*)d_in[4];
    const float* Wu    = (const float*)d_in[5];
    const float* gamma = (const float*)d_in[6];
    const float* beta  = (const float*)d_in[7];
    float* out = (float*)d_out;

    zero_kernel<<<1024, 256>>>();
    prep_kernel<<<(HIDDEN * HIDDEN + 255) / 256, 256>>>(W3, Wu);
    uv_kernel<<<(N_NODES + UV_ROWS - 1) / UV_ROWS, dim3(HIDDEN, UV_ROWS)>>>(h, Wu);
    triple_kernel<<<4096, 256>>>(idx, d1, d2);
    final_kernel<<<(N_NODES + 15) / 16, dim3(16, 16)>>>(h, gamma, beta, out);
}

// round 3
// speedup vs baseline: 1.3692x; 1.3692x over previous
#include <cuda_runtime.h>
#include <cuda_fp16.h>

#define N_NODES   100000
#define HIDDEN    48
#define N_TRIPLES 2000000
#define ROW_PAD   64          // u/v rows padded to 64 halves = 128 B

__device__ __align__(16) __half g_u[N_NODES * ROW_PAD];
__device__ __align__(16) __half g_v[N_NODES * ROW_PAD];
__device__ __align__(16) float  g_agg[N_NODES * HIDDEN];
__device__ __align__(16) float  g_cnt[N_NODES];
__device__ __align__(16) float  g_C2[HIDDEN * HIDDEN];

// ---------------------------------------------------------------------------
// Zero accumulators (graph replays require this every launch)
// ---------------------------------------------------------------------------
__global__ void zero_kernel() {
    int i = blockIdx.x * blockDim.x + threadIdx.x;
    int stride = gridDim.x * blockDim.x;
    float4* a = (float4*)g_agg;
    const int n4 = N_NODES * HIDDEN / 4;
    for (int k = i; k < n4; k += stride) a[k] = make_float4(0.f, 0.f, 0.f, 0.f);
    for (int k = i; k < N_NODES; k += stride) g_cnt[k] = 0.f;
}

// ---------------------------------------------------------------------------
// C2[k][o] = sum_j W3[j][k] * Wu[o][48+j]
// ---------------------------------------------------------------------------
__global__ void prep_kernel(const float* __restrict__ W3,
                            const float* __restrict__ Wu) {
    int i = blockIdx.x * blockDim.x + threadIdx.x;
    if (i < HIDDEN * HIDDEN) {
        int k = i / HIDDEN, o = i % HIDDEN;
        float s = 0.f;
        #pragma unroll
        for (int j = 0; j < HIDDEN; j++)
            s = fmaf(W3[j * HIDDEN + k], Wu[o * 2 * HIDDEN + HIDDEN + j], s);
        g_C2[i] = s;
    }
}

// ---------------------------------------------------------------------------
// u[n][o] = h[n]·Wu1[o];  v[n][o] = h[n]·C2[:,o]   -> stored fp16, 64-padded.
// blockDim (12, 32): tx = col-quad (4 cols via float4 weight loads),
// ty handles rows {ty, ty+32} of a 64-row tile. 16 accumulators/thread.
// ---------------------------------------------------------------------------
__global__ void uv_kernel(const float* __restrict__ h,
                          const float* __restrict__ Wu) {
    __shared__ float4 sA[HIDDEN][12];      // sA[k][c4] = Wu1 cols 4c4..4c4+3 at row k
    __shared__ float4 sC[HIDDEN][12];      // same for C2
    __shared__ float  sh[64][49];          // 64 h rows, padded stride

    int tx = threadIdx.x;                  // 0..11
    int ty = threadIdx.y;                  // 0..31
    int tid = ty * 12 + tx;                // 0..383

    for (int i = tid; i < HIDDEN * 12; i += 384) {
        int k = i / 12, c4 = i % 12;
        sA[k][c4] = make_float4(Wu[(4*c4+0) * 2*HIDDEN + k],
                                Wu[(4*c4+1) * 2*HIDDEN + k],
                                Wu[(4*c4+2) * 2*HIDDEN + k],
                                Wu[(4*c4+3) * 2*HIDDEN + k]);
        sC[k][c4] = ((const float4*)g_C2)[k * 12 + c4];
    }
    int rowBase = blockIdx.x * 64;
    for (int i = tid; i < 64 * 12; i += 384) {
        int r = i / 12, c4 = i % 12;
        int row = rowBase + r;
        float4 v = (row < N_NODES) ? ((const float4*)(h + row * HIDDEN))[c4]
                                   : make_float4(0.f, 0.f, 0.f, 0.f);
        sh[r][4*c4+0] = v.x; sh[r][4*c4+1] = v.y;
        sh[r][4*c4+2] = v.z; sh[r][4*c4+3] = v.w;
    }
    __syncthreads();

    int r0 = ty, r1 = ty + 32;
    float4 u0 = make_float4(0,0,0,0), u1 = u0, v0 = u0, v1 = u0;
    #pragma unroll
    for (int k = 0; k < HIDDEN; k++) {
        float4 wa = sA[k][tx];
        float4 wc = sC[k][tx];
        float h0 = sh[r0][k];
        float h1 = sh[r1][k];
        u0.x = fmaf(h0, wa.x, u0.x); u0.y = fmaf(h0, wa.y, u0.y);
        u0.z = fmaf(h0, wa.z, u0.z); u0.w = fmaf(h0, wa.w, u0.w);
        u1.x = fmaf(h1, wa.x, u1.x); u1.y = fmaf(h1, wa.y, u1.y);
        u1.z = fmaf(h1, wa.z, u1.z); u1.w = fmaf(h1, wa.w, u1.w);
        v0.x = fmaf(h0, wc.x, v0.x); v0.y = fmaf(h0, wc.y, v0.y);
        v0.z = fmaf(h0, wc.z, v0.z); v0.w = fmaf(h0, wc.w, v0.w);
        v1.x = fmaf(h1, wc.x, v1.x); v1.y = fmaf(h1, wc.y, v1.y);
        v1.z = fmaf(h1, wc.z, v1.z); v1.w = fmaf(h1, wc.w, v1.w);
    }

    int row0 = rowBase + r0, row1 = rowBase + r1;
    if (row0 < N_NODES) {
        union { __half2 h2[2]; uint2 u; } cu, cv;
        cu.h2[0] = __floats2half2_rn(u0.x, u0.y); cu.h2[1] = __floats2half2_rn(u0.z, u0.w);
        cv.h2[0] = __floats2half2_rn(v0.x, v0.y); cv.h2[1] = __floats2half2_rn(v0.z, v0.w);
        ((uint2*)(g_u + row0 * ROW_PAD))[tx] = cu.u;
        ((uint2*)(g_v + row0 * ROW_PAD))[tx] = cv.u;
    }
    if (row1 < N_NODES) {
        union { __half2 h2[2]; uint2 u; } cu, cv;
        cu.h2[0] = __floats2half2_rn(u1.x, u1.y); cu.h2[1] = __floats2half2_rn(u1.z, u1.w);
        cv.h2[0] = __floats2half2_rn(v1.x, v1.y); cv.h2[1] = __floats2half2_rn(v1.z, v1.w);
        ((uint2*)(g_u + row1 * ROW_PAD))[tx] = cu.u;
        ((uint2*)(g_v + row1 * ROW_PAD))[tx] = cv.u;
    }
}

// ---------------------------------------------------------------------------
// Per-triple gather (fp16, 1 line per row) + leaky + weighted fp32 v4 scatter.
// 2 triples/warp; lanes j<12 handle 4 cols each; lane j==12 counts.
// ---------------------------------------------------------------------------
__global__ void triple_kernel(const int* __restrict__ idx,
                              const float* __restrict__ d1a,
                              const float* __restrict__ d2a) {
    int gtid = blockIdx.x * blockDim.x + threadIdx.x;
    int warpId = gtid >> 5;
    int nWarps = (gridDim.x * blockDim.x) >> 5;
    int lane = threadIdx.x & 31;
    int half = lane >> 4;
    int j = lane & 15;
    const int nPairs = N_TRIPLES / 2;

    for (int p = warpId; p < nPairs; p += nWarps) {
        int t = 2 * p + half;
        int b = 3 * t;
        int c  = idx[b];
        int n1 = idx[b + 1];
        int n2 = idx[b + 2];
        float d1 = __ldg(d1a + t);
        float d2 = __ldg(d2a + t);
        float w = 1.0f + 0.3f * (fabsf(d1 - d2) / (fmaxf(d1, d2) + 1e-8f));

        if (j < 12) {
            uint2 au = ((const uint2*)(g_u + c  * ROW_PAD))[j];
            uint2 a1 = ((const uint2*)(g_v + n1 * ROW_PAD))[j];
            uint2 a2 = ((const uint2*)(g_v + n2 * ROW_PAD))[j];
            float2 u0 = __half22float2(*(__half2*)&au.x);
            float2 u1 = __half22float2(*(__half2*)&au.y);
            float2 p0 = __half22float2(*(__half2*)&a1.x);
            float2 p1 = __half22float2(*(__half2*)&a1.y);
            float2 q0 = __half22float2(*(__half2*)&a2.x);
            float2 q1 = __half22float2(*(__half2*)&a2.y);
            float x0 = u0.x + p0.x + q0.x;
            float x1 = u0.y + p0.y + q0.y;
            float x2 = u1.x + p1.x + q1.x;
            float x3 = u1.y + p1.y + q1.y;
            float dx = (x0 > 0.f ? x0 : 0.01f * x0) * w;
            float dy = (x1 > 0.f ? x1 : 0.01f * x1) * w;
            float dz = (x2 > 0.f ? x2 : 0.01f * x2) * w;
            float dw = (x3 > 0.f ? x3 : 0.01f * x3) * w;
            float* dst = g_agg + c * HIDDEN + 4 * j;
            asm volatile("red.global.add.v4.f32 [%0], {%1, %2, %3, %4};"
                         :: "l"(dst), "f"(dx), "f"(dy), "f"(dz), "f"(dw)
                         : "memory");
        } else if (j == 12) {
            atomicAdd(&g_cnt[c], 1.0f);
        }
    }
}

// ---------------------------------------------------------------------------
// out = LayerNorm(h + agg / sqrt(max(cnt,1))) * gamma + beta
// ---------------------------------------------------------------------------
__global__ void final_kernel(const float* __restrict__ h,
                             const float* __restrict__ gamma,
                             const float* __restrict__ beta,
                             float* __restrict__ out) {
    int tx = threadIdx.x;  // 0..15
    int ty = threadIdx.y;  // 0..15
    int row = blockIdx.x * 16 + ty;
    if (row >= N_NODES) return;

    float rs = rsqrtf(fmaxf(g_cnt[row], 1.0f));
    int base = row * HIDDEN + tx * 3;
    float x0 = h[base]     + g_agg[base]     * rs;
    float x1 = h[base + 1] + g_agg[base + 1] * rs;
    float x2 = h[base + 2] + g_agg[base + 2] * rs;

    float s = x0 + x1 + x2;
    #pragma unroll
    for (int m = 8; m; m >>= 1) s += __shfl_xor_sync(0xffffffffu, s, m);
    float mu = s * (1.f / 48.f);

    float e0 = x0 - mu, e1 = x1 - mu, e2 = x2 - mu;
    float q = e0 * e0 + e1 * e1 + e2 * e2;
    #pragma unroll
    for (int m = 8; m; m >>= 1) q += __shfl_xor_sync(0xffffffffu, q, m);
    float inv = rsqrtf(q * (1.f / 48.f) + 1e-5f);

    int o = tx * 3;
    out[base]     = e0 * inv * gamma[o]     + beta[o];
    out[base + 1] = e1 * inv * gamma[o + 1] + beta[o + 1];
    out[base + 2] = e2 * inv * gamma[o + 2] + beta[o + 2];
}

// ---------------------------------------------------------------------------
extern "C" void kernel_launch(void* const* d_in, const int* in_sizes, int n_in,
                              void* d_out, int out_size) {
    const float* h     = (const float*)d_in[0];
    const int*   idx   = (const int*)d_in[1];
    const float* d1    = (const float*)d_in[2];
    const float* d2    = (const float*)d_in[3];
    const float* W3    = (const float*)d_in[4];
    const float* Wu    = (const float*)d_in[5];
    const float* gamma = (const float*)d_in[6];
    const float* beta  = (const float*)d_in[7];
    float* out = (float*)d_out;

    zero_kernel<<<1024, 256>>>();
    prep_kernel<<<(HIDDEN * HIDDEN + 255) / 256, 256>>>(W3, Wu);
    uv_kernel<<<(N_NODES + 63) / 64, dim3(12, 32)>>>(h, Wu);
    triple_kernel<<<4096, 256>>>(idx, d1, d2);
    final_kernel<<<(N_NODES + 15) / 16, dim3(16, 16)>>>(h, gamma, beta, out);
}

// round 4
// speedup vs baseline: 1.4617x; 1.0675x over previous
#include <cuda_runtime.h>
#include <cuda_fp16.h>

#define N_NODES   100000
#define HIDDEN    48
#define N_TRIPLES 2000000
#define ROW_PAD   64          // v rows padded to 64 halves = 128 B

__device__ __align__(16) float  g_u[N_NODES * HIDDEN];     // fp32 u
__device__ __align__(16) __half g_v[N_NODES * ROW_PAD];    // fp16 v
__device__ __align__(16) float  g_agg[N_NODES * HIDDEN];   // zero-maintained
__device__ __align__(16) float  g_cnt[N_NODES];            // zero-maintained
__device__ __align__(16) float  g_C2[HIDDEN * HIDDEN];
__device__ __align__(16) int4   g_rec[N_TRIPLES];          // {c, n1, n2, w_bits}

// ---------------------------------------------------------------------------
// C2[k][o] = sum_j W3[j][k] * Wu[o][48+j]
// ---------------------------------------------------------------------------
__global__ void prep_kernel(const float* __restrict__ W3,
                            const float* __restrict__ Wu) {
    int i = blockIdx.x * blockDim.x + threadIdx.x;
    if (i < HIDDEN * HIDDEN) {
        int k = i / HIDDEN, o = i % HIDDEN;
        float s = 0.f;
        #pragma unroll
        for (int j = 0; j < HIDDEN; j++)
            s = fmaf(W3[j * HIDDEN + k], Wu[o * 2 * HIDDEN + HIDDEN + j], s);
        g_C2[i] = s;
    }
}

// ---------------------------------------------------------------------------
// Pack per-triple record {c, n1, n2, w} and accumulate center counts.
// (g_cnt is zero on entry: zero-init at load, re-zeroed by final_kernel.)
// ---------------------------------------------------------------------------
__global__ void pack_kernel(const int* __restrict__ idx,
                            const float* __restrict__ d1a,
                            const float* __restrict__ d2a) {
    int t = blockIdx.x * blockDim.x + threadIdx.x;
    if (t < N_TRIPLES) {
        int c  = idx[3 * t];
        int n1 = idx[3 * t + 1];
        int n2 = idx[3 * t + 2];
        float d1 = __ldg(d1a + t);
        float d2 = __ldg(d2a + t);
        float w = 1.0f + 0.3f * (fabsf(d1 - d2) / (fmaxf(d1, d2) + 1e-8f));
        g_rec[t] = make_int4(c, n1, n2, __float_as_int(w));
        asm volatile("red.global.add.f32 [%0], %1;"
                     :: "l"(g_cnt + c), "f"(1.0f) : "memory");
    }
}

// ---------------------------------------------------------------------------
// u[n][o] = h[n]·Wu1[o] (fp32);  v[n][o] = h[n]·C2[:,o] (fp16, 64-padded)
// blockDim (12, 32)
// ---------------------------------------------------------------------------
__global__ void uv_kernel(const float* __restrict__ h,
                          const float* __restrict__ Wu) {
    __shared__ float4 sA[HIDDEN][12];
    __shared__ float4 sC[HIDDEN][12];
    __shared__ float  sh[64][49];

    int tx = threadIdx.x;                  // 0..11
    int ty = threadIdx.y;                  // 0..31
    int tid = ty * 12 + tx;

    for (int i = tid; i < HIDDEN * 12; i += 384) {
        int k = i / 12, c4 = i % 12;
        sA[k][c4] = make_float4(Wu[(4*c4+0) * 2*HIDDEN + k],
                                Wu[(4*c4+1) * 2*HIDDEN + k],
                                Wu[(4*c4+2) * 2*HIDDEN + k],
                                Wu[(4*c4+3) * 2*HIDDEN + k]);
        sC[k][c4] = ((const float4*)g_C2)[k * 12 + c4];
    }
    int rowBase = blockIdx.x * 64;
    for (int i = tid; i < 64 * 12; i += 384) {
        int r = i / 12, c4 = i % 12;
        int row = rowBase + r;
        float4 v = (row < N_NODES) ? ((const float4*)(h + row * HIDDEN))[c4]
                                   : make_float4(0.f, 0.f, 0.f, 0.f);
        sh[r][4*c4+0] = v.x; sh[r][4*c4+1] = v.y;
        sh[r][4*c4+2] = v.z; sh[r][4*c4+3] = v.w;
    }
    __syncthreads();

    int r0 = ty, r1 = ty + 32;
    float4 u0 = make_float4(0,0,0,0), u1 = u0, v0 = u0, v1 = u0;
    #pragma unroll
    for (int k = 0; k < HIDDEN; k++) {
        float4 wa = sA[k][tx];
        float4 wc = sC[k][tx];
        float h0 = sh[r0][k];
        float h1 = sh[r1][k];
        u0.x = fmaf(h0, wa.x, u0.x); u0.y = fmaf(h0, wa.y, u0.y);
        u0.z = fmaf(h0, wa.z, u0.z); u0.w = fmaf(h0, wa.w, u0.w);
        u1.x = fmaf(h1, wa.x, u1.x); u1.y = fmaf(h1, wa.y, u1.y);
        u1.z = fmaf(h1, wa.z, u1.z); u1.w = fmaf(h1, wa.w, u1.w);
        v0.x = fmaf(h0, wc.x, v0.x); v0.y = fmaf(h0, wc.y, v0.y);
        v0.z = fmaf(h0, wc.z, v0.z); v0.w = fmaf(h0, wc.w, v0.w);
        v1.x = fmaf(h1, wc.x, v1.x); v1.y = fmaf(h1, wc.y, v1.y);
        v1.z = fmaf(h1, wc.z, v1.z); v1.w = fmaf(h1, wc.w, v1.w);
    }

    int row0 = rowBase + r0, row1 = rowBase + r1;
    if (row0 < N_NODES) {
        ((float4*)(g_u + row0 * HIDDEN))[tx] = u0;
        union { __half2 h2[2]; uint2 u; } cv;
        cv.h2[0] = __floats2half2_rn(v0.x, v0.y); cv.h2[1] = __floats2half2_rn(v0.z, v0.w);
        ((uint2*)(g_v + row0 * ROW_PAD))[tx] = cv.u;
    }
    if (row1 < N_NODES) {
        ((float4*)(g_u + row1 * HIDDEN))[tx] = u1;
        union { __half2 h2[2]; uint2 u; } cv;
        cv.h2[0] = __floats2half2_rn(v1.x, v1.y); cv.h2[1] = __floats2half2_rn(v1.z, v1.w);
        ((uint2*)(g_v + row1 * ROW_PAD))[tx] = cv.u;
    }
}

// ---------------------------------------------------------------------------
// Per-triple: rec load + u(fp32)/v(fp16) gather + half2 add + leaky*w + v4 RED.
// 2 triples per warp per stage, 2 stages unrolled (4 triples/warp-iter).
// ---------------------------------------------------------------------------
__device__ __forceinline__ void process_triple(int t, int j) {
    int4 r = __ldg(&g_rec[t]);
    float w = __int_as_float(r.w);
    if (j < 12) {
        float4 uu = __ldg((const float4*)(g_u + r.x * HIDDEN) + j);
        uint2 a1  = __ldg((const uint2*)(g_v + r.y * ROW_PAD) + j);
        uint2 a2  = __ldg((const uint2*)(g_v + r.z * ROW_PAD) + j);
        __half2 s0 = __hadd2(*(__half2*)&a1.x, *(__half2*)&a2.x);
        __half2 s1 = __hadd2(*(__half2*)&a1.y, *(__half2*)&a2.y);
        float2 f0 = __half22float2(s0);
        float2 f1 = __half22float2(s1);
        float x0 = uu.x + f0.x;
        float x1 = uu.y + f0.y;
        float x2 = uu.z + f1.x;
        float x3 = uu.w + f1.y;
        float w01 = 0.01f * w;
        float dx = fmaf(fminf(x0, 0.f), w01, fmaxf(x0, 0.f) * w);
        float dy = fmaf(fminf(x1, 0.f), w01, fmaxf(x1, 0.f) * w);
        float dz = fmaf(fminf(x2, 0.f), w01, fmaxf(x2, 0.f) * w);
        float dw = fmaf(fminf(x3, 0.f), w01, fmaxf(x3, 0.f) * w);
        float* dst = g_agg + r.x * HIDDEN + 4 * j;
        asm volatile("red.global.add.v4.f32 [%0], {%1, %2, %3, %4};"
                     :: "l"(dst), "f"(dx), "f"(dy), "f"(dz), "f"(dw)
                     : "memory");
    }
}

__global__ void __launch_bounds__(256) triple_kernel() {
    int gtid = blockIdx.x * blockDim.x + threadIdx.x;
    int warpId = gtid >> 5;
    int nWarps = (gridDim.x * blockDim.x) >> 5;
    int lane = threadIdx.x & 31;
    int half = lane >> 4;
    int j = lane & 15;

    // N_TRIPLES % 4 == 0, warp handles 4 consecutive triples per iter
    for (int base = warpId * 4; base < N_TRIPLES; base += nWarps * 4) {
        process_triple(base + half, j);
        process_triple(base + 2 + half, j);
    }
}

// ---------------------------------------------------------------------------
// out = LayerNorm(h + agg / sqrt(max(cnt,1))); then re-zero agg/cnt for the
// next graph replay (globals start zero-initialized at module load).
// ---------------------------------------------------------------------------
__global__ void final_kernel(const float* __restrict__ h,
                             const float* __restrict__ gamma,
                             const float* __restrict__ beta,
                             float* __restrict__ out) {
    int tx = threadIdx.x;  // 0..15
    int ty = threadIdx.y;  // 0..15
    int row = blockIdx.x * 16 + ty;
    if (row >= N_NODES) return;

    float rs = rsqrtf(fmaxf(g_cnt[row], 1.0f));
    int base = row * HIDDEN + tx * 3;
    float x0 = h[base]     + g_agg[base]     * rs;
    float x1 = h[base + 1] + g_agg[base + 1] * rs;
    float x2 = h[base + 2] + g_agg[base + 2] * rs;

    // re-zero for next replay (each thread zeroes exactly what it read)
    g_agg[base] = 0.f; g_agg[base + 1] = 0.f; g_agg[base + 2] = 0.f;
    if (tx == 0) g_cnt[row] = 0.f;

    float s = x0 + x1 + x2;
    #pragma unroll
    for (int m = 8; m; m >>= 1) s += __shfl_xor_sync(0xffffffffu, s, m);
    float mu = s * (1.f / 48.f);

    float e0 = x0 - mu, e1 = x1 - mu, e2 = x2 - mu;
    float q = e0 * e0 + e1 * e1 + e2 * e2;
    #pragma unroll
    for (int m = 8; m; m >>= 1) q += __shfl_xor_sync(0xffffffffu, q, m);
    float inv = rsqrtf(q * (1.f / 48.f) + 1e-5f);

    int o = tx * 3;
    out[base]     = e0 * inv * gamma[o]     + beta[o];
    out[base + 1] = e1 * inv * gamma[o + 1] + beta[o + 1];
    out[base + 2] = e2 * inv * gamma[o + 2] + beta[o + 2];
}

// ---------------------------------------------------------------------------
extern "C" void kernel_launch(void* const* d_in, const int* in_sizes, int n_in,
                              void* d_out, int out_size) {
    const float* h     = (const float*)d_in[0];
    const int*   idx   = (const int*)d_in[1];
    const float* d1    = (const float*)d_in[2];
    const float* d2    = (const float*)d_in[3];
    const float* W3    = (const float*)d_in[4];
    const float* Wu    = (const float*)d_in[5];
    const float* gamma = (const float*)d_in[6];
    const float* beta  = (const float*)d_in[7];
    float* out = (float*)d_out;

    prep_kernel<<<(HIDDEN * HIDDEN + 255) / 256, 256>>>(W3, Wu);
    pack_kernel<<<(N_TRIPLES + 255) / 256, 256>>>(idx, d1, d2);
    uv_kernel<<<(N_NODES + 63) / 64, dim3(12, 32)>>>(h, Wu);
    triple_kernel<<<4096, 256>>>();
    final_kernel<<<(N_NODES + 15) / 16, dim3(16, 16)>>>(h, gamma, beta, out);
}